// round 9
// baseline (speedup 1.0000x reference)
#include <cuda_runtime.h>
#include <math.h>

// Problem constants
#define TT     2048
#define EE     768
#define HH     512          // H2
#define GATES  2048         // 4*H2
#define KK     7
#define START_TAG 5
#define STOP_TAG  6
#define NEGV  -10000.0f

#define CPD    64           // CTAs per direction in the recurrence
#define UPB    8            // hidden units per CTA (1 per warp)
#define NCH    128          // 16B chunks per direction (HH/4)

// ---------------- scratch (device globals; no runtime allocation) ----------
// gate pre-activations, gate-interleaved: g_preP[dir][t][unit] = {i,f,g,o}
__device__ float4 g_preP[2][TT][HH];        // 32 MB (no priming needed)
__device__ float  g_hs[TT][2 * HH];         // 8 MB concat hidden states
__device__ float  g_feats[TT][KK];
// h broadcast: 16B value in a 32B slot -> 4 chunks/128B line (256 pollers/line,
// half of compact layout) while staying 16.8 MB (L2-resident; not R4's 67MB).
// Each value chunk is written by exactly ONE STG.128 (single-writer rule).
struct HSlot { float4 v; float4 pad; };
__device__ HSlot g_hx[TT + 1][2][NCH];

// ---------------------------------------------------------------------------
// f32x2 packed helpers (exact fp32 semantics, 2x FFMA throughput)
// ---------------------------------------------------------------------------
__device__ __forceinline__ void ffma2(unsigned long long& acc,
                                      unsigned long long a,
                                      unsigned long long b) {
    asm("fma.rn.f32x2 %0, %1, %2, %0;" : "+l"(acc) : "l"(a), "l"(b));
}
__device__ __forceinline__ unsigned long long pack2(float lo, float hi) {
    unsigned long long r;
    asm("mov.b64 %0, {%1, %2};" : "=l"(r) : "f"(lo), "f"(hi));
    return r;
}
__device__ __forceinline__ void unpack2(unsigned long long v, float& lo, float& hi) {
    asm("mov.b64 {%0, %1}, %2;" : "=f"(lo), "=f"(hi) : "l"(v));
}
__device__ __forceinline__ float sum2(unsigned long long v) {
    float lo, hi; unpack2(v, lo, hi); return lo + hi;
}
__device__ __forceinline__ float4 ldvol4(const float* p) {
    float4 v;
    asm volatile("ld.volatile.global.v4.f32 {%0,%1,%2,%3}, [%4];"
                 : "=f"(v.x), "=f"(v.y), "=f"(v.z), "=f"(v.w) : "l"(p));
    return v;
}
__device__ __forceinline__ bool ok4(const float4& v) {
    return (v.x == v.x) && (v.y == v.y) && (v.z == v.z) && (v.w == v.w);
}
__device__ __forceinline__ float fsigm(float x) {
    return 1.f / (1.f + __expf(-x));
}
__device__ __forceinline__ float ftanh(float x) {
    return 2.f / (1.f + __expf(-2.f * x)) - 1.f;
}

// ---------------------------------------------------------------------------
// Kernel 0: NaN-prime the value chunk of every slot. grid=TT+1, block=256.
// ---------------------------------------------------------------------------
__global__ void prime_kernel() {
    const float nv = __int_as_float(0x7fc00000);
    const int t = blockIdx.x;
    const int dir = threadIdx.x >> 7;
    const int ch = threadIdx.x & (NCH - 1);
    g_hx[t][dir][ch].v = make_float4(nv, nv, nv, nv);
}

// ---------------------------------------------------------------------------
// Kernel 1: pre = embeds(@dir) @ W_ih^T + (b_ih+b_hh), gate-interleaved out.
// 128x128 tile, BK=8, double-buffered, f32x2 accumulators.
// grid (16,16,2), 256 threads. dir=1 reads A rows reversed.
// ---------------------------------------------------------------------------
#define GBM 128
#define GBN 128
#define GBK 8
__global__ __launch_bounds__(256) void gemm_pre(
        const float* __restrict__ embeds,
        const float* __restrict__ Wihf,
        const float* __restrict__ Wihb,
        const float* __restrict__ bihf, const float* __restrict__ bhhf,
        const float* __restrict__ bihb, const float* __restrict__ bhhb) {
    const int dir = blockIdx.z;
    const float* __restrict__ Wih = dir ? Wihb : Wihf;
    const float* __restrict__ bi  = dir ? bihb : bihf;
    const float* __restrict__ bh  = dir ? bhhb : bhhf;

    __shared__ __align__(16) float As[2][GBK][GBM];
    __shared__ __align__(16) float Bs[2][GBK][GBN];

    const int tid = threadIdx.x;
    const int m0 = blockIdx.y * GBM;
    const int n0 = blockIdx.x * GBN;

    const int lrow = tid >> 1;
    const int lcol = (tid & 1) * 4;
    const int arow = m0 + lrow;
    const int grow = dir ? (TT - 1 - arow) : arow;
    const float* ap = embeds + (size_t)grow * EE + lcol;
    const int nrow = n0 + lrow;                       // interleaved column
    const int prow = (nrow & 3) * HH + (nrow >> 2);   // original W_ih row
    const float* bp = Wih + (size_t)prow * EE + lcol;

    float4 av = *(const float4*)ap;
    float4 bv = *(const float4*)bp;
    As[0][lcol + 0][lrow] = av.x; As[0][lcol + 1][lrow] = av.y;
    As[0][lcol + 2][lrow] = av.z; As[0][lcol + 3][lrow] = av.w;
    Bs[0][lcol + 0][lrow] = bv.x; Bs[0][lcol + 1][lrow] = bv.y;
    Bs[0][lcol + 2][lrow] = bv.z; Bs[0][lcol + 3][lrow] = bv.w;
    __syncthreads();

    const int ty = tid >> 4, tx = tid & 15;
    const int mo = ty * 8, no = tx * 8;
    unsigned long long accp[8][4] = {};

    const int NTILES = EE / GBK;   // 96
    int buf = 0;
    for (int tIdx = 0; tIdx < NTILES; tIdx++) {
        if (tIdx + 1 < NTILES) {
            const int off = (tIdx + 1) * GBK;
            av = *(const float4*)(ap + off);
            bv = *(const float4*)(bp + off);
        }
#pragma unroll
        for (int k = 0; k < GBK; k++) {
            float a[8];
            *(float4*)&a[0] = *(const float4*)&As[buf][k][mo];
            *(float4*)&a[4] = *(const float4*)&As[buf][k][mo + 4];
            unsigned long long b2[4];
            *(ulonglong2*)&b2[0] = *(const ulonglong2*)&Bs[buf][k][no];
            *(ulonglong2*)&b2[2] = *(const ulonglong2*)&Bs[buf][k][no + 4];
#pragma unroll
            for (int i = 0; i < 8; i++) {
                const unsigned long long ad = pack2(a[i], a[i]);
#pragma unroll
                for (int jp = 0; jp < 4; jp++)
                    ffma2(accp[i][jp], ad, b2[jp]);
            }
        }
        if (tIdx + 1 < NTILES) {
            const int nb = buf ^ 1;
            As[nb][lcol + 0][lrow] = av.x; As[nb][lcol + 1][lrow] = av.y;
            As[nb][lcol + 2][lrow] = av.z; As[nb][lcol + 3][lrow] = av.w;
            Bs[nb][lcol + 0][lrow] = bv.x; Bs[nb][lcol + 1][lrow] = bv.y;
            Bs[nb][lcol + 2][lrow] = bv.z; Bs[nb][lcol + 3][lrow] = bv.w;
            __syncthreads();
            buf = nb;
        }
    }

    float bj[8];
#pragma unroll
    for (int j = 0; j < 8; j++) {
        const int n = n0 + no + j;
        const int pn = (n & 3) * HH + (n >> 2);
        bj[j] = bi[pn] + bh[pn];
    }
    const int u0 = (n0 + no) >> 2;    // two whole units per thread
#pragma unroll
    for (int i = 0; i < 8; i++) {
        const int row = m0 + mo + i;
        float acc[8];
#pragma unroll
        for (int jp = 0; jp < 4; jp++)
            unpack2(accp[i][jp], acc[2 * jp], acc[2 * jp + 1]);
        float4 v0, v1;
        v0.x = acc[0] + bj[0]; v0.y = acc[1] + bj[1];
        v0.z = acc[2] + bj[2]; v0.w = acc[3] + bj[3];
        v1.x = acc[4] + bj[4]; v1.y = acc[5] + bj[5];
        v1.z = acc[6] + bj[6]; v1.w = acc[7] + bj[7];
        g_preP[dir][row][u0]     = v0;
        g_preP[dir][row][u0 + 1] = v1;
    }
}

// ---------------------------------------------------------------------------
// Kernel 2: persistent BiLSTM recurrence. grid (64,2), 256 threads.
// R3 sync protocol, 32B-slot buffer (contention fix):
//   publish = h staged in SMEM then 2x STG.128 into slot values; consumers
//   (tid<128) tight-poll one 16B value each; own chunks short-circuit via
//   SMEM; NaN-primed; 16.8MB buffer stays L2-resident.
// ---------------------------------------------------------------------------
__global__ __launch_bounds__(256, 1) void lstm_rec(
        const float* __restrict__ h0,
        const float* __restrict__ c0,
        const float* __restrict__ Whhf,
        const float* __restrict__ Whhb) {
    __shared__ __align__(16) float4 hsm4[2][NCH];
    __shared__ __align__(16) float h8[UPB];
    const int dir  = blockIdx.y;
    const int sub  = blockIdx.x;
    const int tid  = threadIdx.x;
    const int w    = tid >> 5;
    const int lane = tid & 31;
    const int gu   = sub * UPB + w;            // global hidden unit

    const float* __restrict__ Whh = dir ? Whhb : Whhf;

    // gate weights packed f32x2: Wp[g][2i],Wp[g][2i+1] cover h[(lane+32i)*4..+3]
    unsigned long long Wp[4][8];
#pragma unroll
    for (int g = 0; g < 4; g++) {
        const ulonglong2* row =
            (const ulonglong2*)(Whh + (size_t)(g * HH + gu) * HH);
#pragma unroll
        for (int i = 0; i < 4; i++) {
            ulonglong2 wp = row[lane + 32 * i];
            Wp[g][2 * i]     = wp.x;
            Wp[g][2 * i + 1] = wp.y;
        }
    }
    float c = c0[dir * HH + gu];
    float4 px = __ldg((const float4*)&g_preP[dir][0][gu]);

    for (int t = 0; t < TT; t++) {
        const int buf = t & 1;
        // prefetch next pre-activation (gemm complete; plain load)
        float4 pn = make_float4(0.f, 0.f, 0.f, 0.f);
        if (t + 1 < TT) pn = __ldg((const float4*)&g_preP[dir][t + 1][gu]);

        // acquire h(t) into hsm4[buf]
        if (tid < NCH) {
            float4 hv;
            if (t == 0) {
                hv = ((const float4*)h0)[dir * (HH / 4) + tid];
            } else if ((tid >> 1) == sub) {
                hv = ((const float4*)h8)[tid & 1];       // own chunk via SMEM
            } else {
                const float* pp = (const float*)&g_hx[t][dir][tid].v;
                for (;;) {
                    hv = ldvol4(pp);
                    if (ok4(hv)) break;
                }
            }
            hsm4[buf][tid] = hv;
        }
        __syncthreads();

        // dot: 4 gates x 512 via packed f32x2 FMA
        unsigned long long acc[4][2] = {};
        const ulonglong2* hp = (const ulonglong2*)&hsm4[buf][0];
#pragma unroll
        for (int i = 0; i < 4; i++) {
            const ulonglong2 h2 = hp[lane + 32 * i];
#pragma unroll
            for (int g = 0; g < 4; g++) {
                ffma2(acc[g][0], h2.x, Wp[g][2 * i]);
                ffma2(acc[g][1], h2.y, Wp[g][2 * i + 1]);
            }
        }
        float a0 = sum2(acc[0][0]) + sum2(acc[0][1]);
        float a1 = sum2(acc[1][0]) + sum2(acc[1][1]);
        float a2 = sum2(acc[2][0]) + sum2(acc[2][1]);
        float a3 = sum2(acc[3][0]) + sum2(acc[3][1]);

#pragma unroll
        for (int off = 16; off > 0; off >>= 1) {
            a0 += __shfl_xor_sync(0xffffffffu, a0, off);
            a1 += __shfl_xor_sync(0xffffffffu, a1, off);
            a2 += __shfl_xor_sync(0xffffffffu, a2, off);
            a3 += __shfl_xor_sync(0xffffffffu, a3, off);
        }

        const float ig = fsigm(px.x + a0);
        const float fg = fsigm(px.y + a1);
        const float og = fsigm(px.w + a3);
        c = fg * c + ig * ftanh(px.z + a2);
        const float hn = og * ftanh(c);

        if (lane == 0) {
            h8[w] = hn;
            const int trow = dir ? (TT - 1 - t) : t;
            g_hs[trow][dir * HH + gu] = hn;   // off critical path
        }
        __syncthreads();                      // h8 complete; hsm reusable

        if (tid < 2) {                        // publish via 2x STG.128
            const float4 v = ((const float4*)h8)[tid];
            float* dst = (float*)&g_hx[t + 1][dir][sub * 2 + tid].v;
            asm volatile("st.volatile.global.v4.f32 [%0], {%1,%2,%3,%4};"
                         :: "l"(dst), "f"(v.x), "f"(v.y), "f"(v.z), "f"(v.w)
                         : "memory");
        }
        px = pn;
    }
}

// ---------------------------------------------------------------------------
// Kernel 3: feats = [hs_f | hs_b] @ W_out^T + b_out   (grid = T, 256 threads)
// ---------------------------------------------------------------------------
__global__ void feats_kernel(const float* __restrict__ Wout,
                             const float* __restrict__ bout) {
    __shared__ __align__(16) float hsm[2 * HH];
    const int t = blockIdx.x;
    const int tid = threadIdx.x, w = tid >> 5, lane = tid & 31;
    ((float4*)hsm)[tid] = ((const float4*)&g_hs[t][0])[tid];
    __syncthreads();
    if (w < KK) {
        float acc = 0.f;
        const float* wr = Wout + w * 2 * HH;
        for (int k = lane; k < 2 * HH; k += 32) acc += hsm[k] * __ldg(wr + k);
#pragma unroll
        for (int off = 16; off; off >>= 1) acc += __shfl_down_sync(0xffffffffu, acc, off);
        if (lane == 0) g_feats[t][w] = acc + bout[w];
    }
}

// ---------------------------------------------------------------------------
// Kernel 4: Viterbi forward + backtrace. 1 block, 128 threads; feats in SMEM.
// ---------------------------------------------------------------------------
__global__ void viterbi_kernel(const float* __restrict__ trans,
                               float* __restrict__ out) {
    extern __shared__ __align__(16) float fsm[];   // [TT][KK] = 57344 B
    __shared__ signed char bp[TT][8];
    __shared__ signed char path_s[TT];
    const int tid = threadIdx.x;
    const int lane = tid & 31;

    {
        const float4* src = (const float4*)&g_feats[0][0];
        float4* dst = (float4*)fsm;
        const int n4 = TT * KK / 4;   // 3584
        for (int i = tid; i < n4; i += blockDim.x) dst[i] = src[i];
    }
    __syncthreads();

    if (tid < 32) {
        float tr[KK];
        if (lane < KK) {
#pragma unroll
            for (int j = 0; j < KK; j++) tr[j] = trans[lane * KK + j];
        }
        float fv = (lane == START_TAG) ? 0.f : NEGV;
        float fvv[KK];
#pragma unroll
        for (int j = 0; j < KK; j++) fvv[j] = __shfl_sync(0xffffffffu, fv, j);

        for (int t = 0; t < TT; t++) {
            if (lane < KK) {
                float v[KK];
#pragma unroll
                for (int j = 0; j < KK; j++) v[j] = fvv[j] + tr[j];
                // left-biased tree argmax (== first-max over j)
                float m01 = v[0]; int i01 = 0;
                if (v[1] > m01) { m01 = v[1]; i01 = 1; }
                float m23 = v[2]; int i23 = 2;
                if (v[3] > m23) { m23 = v[3]; i23 = 3; }
                float m45 = v[4]; int i45 = 4;
                if (v[5] > m45) { m45 = v[5]; i45 = 5; }
                float mA = m01; int iA = i01;
                if (m23 > mA) { mA = m23; iA = i23; }
                float mB = m45; int iB = i45;
                if (v[6] > mB) { mB = v[6]; iB = 6; }
                float m = mA; int im = iA;
                if (mB > m) { m = mB; im = iB; }
                bp[t][lane] = (signed char)im;
                fv = m + fsm[t * KK + lane];
            }
#pragma unroll
            for (int j = 0; j < KK; j++) fvv[j] = __shfl_sync(0xffffffffu, fv, j);
        }

        if (lane == 0) {
            float best = -1e30f; int bi = 0;
#pragma unroll
            for (int i = 0; i < KK; i++) {
                float v = fvv[i] + trans[STOP_TAG * KK + i];
                if (v > best) { best = v; bi = i; }
            }
            out[0] = best;                         // path_score
            int tag = bi;
            for (int t = TT - 1; t >= 0; t--) {
                path_s[t] = (signed char)tag;
                tag = bp[t][tag];
            }
        }
    }
    __syncthreads();
    for (int t = tid; t < TT; t += blockDim.x) out[1 + t] = (float)path_s[t];
}

// ---------------------------------------------------------------------------
extern "C" void kernel_launch(void* const* d_in, const int* in_sizes, int n_in,
                              void* d_out, int out_size) {
    const float* embeds = (const float*)d_in[0];
    const float* h0     = (const float*)d_in[1];
    const float* c0     = (const float*)d_in[2];
    const float* Wihf   = (const float*)d_in[3];
    const float* Whhf   = (const float*)d_in[4];
    const float* bihf   = (const float*)d_in[5];
    const float* bhhf   = (const float*)d_in[6];
    const float* Wihb   = (const float*)d_in[7];
    const float* Whhb   = (const float*)d_in[8];
    const float* bihb   = (const float*)d_in[9];
    const float* bhhb   = (const float*)d_in[10];
    const float* Wout   = (const float*)d_in[11];
    const float* bout   = (const float*)d_in[12];
    const float* trans  = (const float*)d_in[13];
    float* out = (float*)d_out;

    const int vit_smem = TT * KK * (int)sizeof(float);   // 57344
    cudaFuncSetAttribute(viterbi_kernel,
                         cudaFuncAttributeMaxDynamicSharedMemorySize, vit_smem);

    prime_kernel<<<TT + 1, 256>>>();
    gemm_pre<<<dim3(GATES / GBN, TT / GBM, 2), 256>>>(embeds, Wihf, Wihb,
                                                      bihf, bhhf, bihb, bhhb);
    lstm_rec<<<dim3(CPD, 2), 256>>>(h0, c0, Whhf, Whhb);
    feats_kernel<<<TT, 256>>>(Wout, bout);
    viterbi_kernel<<<1, 128, vit_smem>>>(trans, out);
}

// round 10
// speedup vs baseline: 1.2373x; 1.2373x over previous
#include <cuda_runtime.h>
#include <math.h>

// Problem constants
#define TT     2048
#define EE     768
#define HH     512          // H2
#define GATES  2048         // 4*H2
#define KK     7
#define START_TAG 5
#define STOP_TAG  6
#define NEGV  -10000.0f

#define CPD    64           // CTAs per direction in the recurrence
#define UPB    8            // hidden units per CTA (1 per warp)
#define NCH    128          // 16B chunks per direction (HH/4)

// ---------------- scratch (device globals; no runtime allocation) ----------
// gate pre-activations, gate-interleaved: g_preP[dir][t][unit] = {i,f,g,o}
__device__ float4 g_preP[2][TT][HH];        // 32 MB (no priming needed)
__device__ float  g_hs[TT][2 * HH];         // 8 MB concat hidden states
__device__ float  g_feats[TT][KK];
// h broadcast: COMPACT layout (8.4 MB, L2-resident), NaN-primed.
// Each 16B chunk is written by exactly ONE STG.128 (single-writer rule).
__device__ float  g_hseq[TT + 1][2][HH];

// ---------------------------------------------------------------------------
// f32x2 packed helpers (exact fp32 semantics, 2x FFMA throughput)
// ---------------------------------------------------------------------------
__device__ __forceinline__ void ffma2(unsigned long long& acc,
                                      unsigned long long a,
                                      unsigned long long b) {
    asm("fma.rn.f32x2 %0, %1, %2, %0;" : "+l"(acc) : "l"(a), "l"(b));
}
__device__ __forceinline__ unsigned long long pack2(float lo, float hi) {
    unsigned long long r;
    asm("mov.b64 %0, {%1, %2};" : "=l"(r) : "f"(lo), "f"(hi));
    return r;
}
__device__ __forceinline__ void unpack2(unsigned long long v, float& lo, float& hi) {
    asm("mov.b64 {%0, %1}, %2;" : "=f"(lo), "=f"(hi) : "l"(v));
}
__device__ __forceinline__ float sum2(unsigned long long v) {
    float lo, hi; unpack2(v, lo, hi); return lo + hi;
}
__device__ __forceinline__ float4 ldvol4(const float* p) {
    float4 v;
    asm volatile("ld.volatile.global.v4.f32 {%0,%1,%2,%3}, [%4];"
                 : "=f"(v.x), "=f"(v.y), "=f"(v.z), "=f"(v.w) : "l"(p));
    return v;
}
__device__ __forceinline__ float fsigm(float x) {
    return 1.f / (1.f + __expf(-x));
}
__device__ __forceinline__ float ftanh(float x) {
    return 2.f / (1.f + __expf(-2.f * x)) - 1.f;
}

// ---------------------------------------------------------------------------
// Kernel 0: NaN-prime g_hseq. Every replay (captured in the graph).
// ---------------------------------------------------------------------------
__global__ void prime_kernel() {
    const float nv = __int_as_float(0x7fc00000);
    const float4 v = make_float4(nv, nv, nv, nv);
    float4* p = (float4*)&g_hseq[0][0][0];
    const int n = (TT + 1) * 2 * HH / 4;
    for (int i = blockIdx.x * blockDim.x + threadIdx.x; i < n;
         i += gridDim.x * blockDim.x)
        p[i] = v;
}

// ---------------------------------------------------------------------------
// Kernel X: no-op spacer so ncu's fixed capture index (3) lands on lstm_rec.
// ---------------------------------------------------------------------------
__global__ void noop_kernel() {}

// ---------------------------------------------------------------------------
// Kernel 1: pre = embeds(@dir) @ W_ih^T + (b_ih+b_hh), gate-interleaved out.
// 128x128 tile, BK=8, double-buffered, f32x2 accumulators.
// grid (16,16,2), 256 threads. dir=1 reads A rows reversed.
// ---------------------------------------------------------------------------
#define GBM 128
#define GBN 128
#define GBK 8
__global__ __launch_bounds__(256) void gemm_pre(
        const float* __restrict__ embeds,
        const float* __restrict__ Wihf,
        const float* __restrict__ Wihb,
        const float* __restrict__ bihf, const float* __restrict__ bhhf,
        const float* __restrict__ bihb, const float* __restrict__ bhhb) {
    const int dir = blockIdx.z;
    const float* __restrict__ Wih = dir ? Wihb : Wihf;
    const float* __restrict__ bi  = dir ? bihb : bihf;
    const float* __restrict__ bh  = dir ? bhhb : bhhf;

    __shared__ __align__(16) float As[2][GBK][GBM];
    __shared__ __align__(16) float Bs[2][GBK][GBN];

    const int tid = threadIdx.x;
    const int m0 = blockIdx.y * GBM;
    const int n0 = blockIdx.x * GBN;

    const int lrow = tid >> 1;
    const int lcol = (tid & 1) * 4;
    const int arow = m0 + lrow;
    const int grow = dir ? (TT - 1 - arow) : arow;
    const float* ap = embeds + (size_t)grow * EE + lcol;
    const int nrow = n0 + lrow;                       // interleaved column
    const int prow = (nrow & 3) * HH + (nrow >> 2);   // original W_ih row
    const float* bp = Wih + (size_t)prow * EE + lcol;

    float4 av = *(const float4*)ap;
    float4 bv = *(const float4*)bp;
    As[0][lcol + 0][lrow] = av.x; As[0][lcol + 1][lrow] = av.y;
    As[0][lcol + 2][lrow] = av.z; As[0][lcol + 3][lrow] = av.w;
    Bs[0][lcol + 0][lrow] = bv.x; Bs[0][lcol + 1][lrow] = bv.y;
    Bs[0][lcol + 2][lrow] = bv.z; Bs[0][lcol + 3][lrow] = bv.w;
    __syncthreads();

    const int ty = tid >> 4, tx = tid & 15;
    const int mo = ty * 8, no = tx * 8;
    unsigned long long accp[8][4] = {};

    const int NTILES = EE / GBK;   // 96
    int buf = 0;
    for (int tIdx = 0; tIdx < NTILES; tIdx++) {
        if (tIdx + 1 < NTILES) {
            const int off = (tIdx + 1) * GBK;
            av = *(const float4*)(ap + off);
            bv = *(const float4*)(bp + off);
        }
#pragma unroll
        for (int k = 0; k < GBK; k++) {
            float a[8];
            *(float4*)&a[0] = *(const float4*)&As[buf][k][mo];
            *(float4*)&a[4] = *(const float4*)&As[buf][k][mo + 4];
            unsigned long long b2[4];
            *(ulonglong2*)&b2[0] = *(const ulonglong2*)&Bs[buf][k][no];
            *(ulonglong2*)&b2[2] = *(const ulonglong2*)&Bs[buf][k][no + 4];
#pragma unroll
            for (int i = 0; i < 8; i++) {
                const unsigned long long ad = pack2(a[i], a[i]);
#pragma unroll
                for (int jp = 0; jp < 4; jp++)
                    ffma2(accp[i][jp], ad, b2[jp]);
            }
        }
        if (tIdx + 1 < NTILES) {
            const int nb = buf ^ 1;
            As[nb][lcol + 0][lrow] = av.x; As[nb][lcol + 1][lrow] = av.y;
            As[nb][lcol + 2][lrow] = av.z; As[nb][lcol + 3][lrow] = av.w;
            Bs[nb][lcol + 0][lrow] = bv.x; Bs[nb][lcol + 1][lrow] = bv.y;
            Bs[nb][lcol + 2][lrow] = bv.z; Bs[nb][lcol + 3][lrow] = bv.w;
            __syncthreads();
            buf = nb;
        }
    }

    float bj[8];
#pragma unroll
    for (int j = 0; j < 8; j++) {
        const int n = n0 + no + j;
        const int pn = (n & 3) * HH + (n >> 2);
        bj[j] = bi[pn] + bh[pn];
    }
    const int u0 = (n0 + no) >> 2;    // two whole units per thread
#pragma unroll
    for (int i = 0; i < 8; i++) {
        const int row = m0 + mo + i;
        float acc[8];
#pragma unroll
        for (int jp = 0; jp < 4; jp++)
            unpack2(accp[i][jp], acc[2 * jp], acc[2 * jp + 1]);
        float4 v0, v1;
        v0.x = acc[0] + bj[0]; v0.y = acc[1] + bj[1];
        v0.z = acc[2] + bj[2]; v0.w = acc[3] + bj[3];
        v1.x = acc[4] + bj[4]; v1.y = acc[5] + bj[5];
        v1.z = acc[6] + bj[6]; v1.w = acc[7] + bj[7];
        g_preP[dir][row][u0]     = v0;
        g_preP[dir][row][u0 + 1] = v1;
    }
}

// ---------------------------------------------------------------------------
// Kernel 2: persistent BiLSTM recurrence. grid (64,2), 256 threads.
// R3/R8 sync protocol: staged single-writer STG.128 publish, compact 8.4MB
// NaN-primed buffer, tight 16B polls (tid<128, one chunk each), own chunks
// short-circuit via SMEM. Changes this round: poll validates ONE word
// (STG.128 gives atomic 16B visibility; h=tanh can't be NaN), and the
// archival g_hs store is moved AFTER the publish.
// ---------------------------------------------------------------------------
__global__ __launch_bounds__(256, 1) void lstm_rec(
        const float* __restrict__ h0,
        const float* __restrict__ c0,
        const float* __restrict__ Whhf,
        const float* __restrict__ Whhb) {
    __shared__ __align__(16) float4 hsm4[2][NCH];
    __shared__ __align__(16) float h8[UPB];
    const int dir  = blockIdx.y;
    const int sub  = blockIdx.x;
    const int tid  = threadIdx.x;
    const int w    = tid >> 5;
    const int lane = tid & 31;
    const int gu   = sub * UPB + w;            // global hidden unit

    const float* __restrict__ Whh = dir ? Whhb : Whhf;

    // gate weights packed f32x2: Wp[g][2i],Wp[g][2i+1] cover h[(lane+32i)*4..+3]
    unsigned long long Wp[4][8];
#pragma unroll
    for (int g = 0; g < 4; g++) {
        const ulonglong2* row =
            (const ulonglong2*)(Whh + (size_t)(g * HH + gu) * HH);
#pragma unroll
        for (int i = 0; i < 4; i++) {
            ulonglong2 wp = row[lane + 32 * i];
            Wp[g][2 * i]     = wp.x;
            Wp[g][2 * i + 1] = wp.y;
        }
    }
    float c = c0[dir * HH + gu];
    float4 px = __ldg((const float4*)&g_preP[dir][0][gu]);

    for (int t = 0; t < TT; t++) {
        const int buf = t & 1;
        // prefetch next pre-activation (gemm complete; plain load)
        float4 pn = make_float4(0.f, 0.f, 0.f, 0.f);
        if (t + 1 < TT) pn = __ldg((const float4*)&g_preP[dir][t + 1][gu]);

        // acquire h(t) into hsm4[buf]
        if (tid < NCH) {
            float4 hv;
            if (t == 0) {
                hv = ((const float4*)h0)[dir * (HH / 4) + tid];
            } else if ((tid >> 1) == sub) {
                hv = ((const float4*)h8)[tid & 1];       // own chunk via SMEM
            } else {
                const float* pp = &g_hseq[t][dir][tid * 4];
                for (;;) {
                    hv = ldvol4(pp);
                    if (hv.x == hv.x) break;   // 16B chunk is single-STG atomic
                }
            }
            hsm4[buf][tid] = hv;
        }
        __syncthreads();

        // dot: 4 gates x 512 via packed f32x2 FMA
        unsigned long long acc[4][2] = {};
        const ulonglong2* hp = (const ulonglong2*)&hsm4[buf][0];
#pragma unroll
        for (int i = 0; i < 4; i++) {
            const ulonglong2 h2 = hp[lane + 32 * i];
#pragma unroll
            for (int g = 0; g < 4; g++) {
                ffma2(acc[g][0], h2.x, Wp[g][2 * i]);
                ffma2(acc[g][1], h2.y, Wp[g][2 * i + 1]);
            }
        }
        float a0 = sum2(acc[0][0]) + sum2(acc[0][1]);
        float a1 = sum2(acc[1][0]) + sum2(acc[1][1]);
        float a2 = sum2(acc[2][0]) + sum2(acc[2][1]);
        float a3 = sum2(acc[3][0]) + sum2(acc[3][1]);

#pragma unroll
        for (int off = 16; off > 0; off >>= 1) {
            a0 += __shfl_xor_sync(0xffffffffu, a0, off);
            a1 += __shfl_xor_sync(0xffffffffu, a1, off);
            a2 += __shfl_xor_sync(0xffffffffu, a2, off);
            a3 += __shfl_xor_sync(0xffffffffu, a3, off);
        }

        const float ig = fsigm(px.x + a0);
        const float fg = fsigm(px.y + a1);
        const float og = fsigm(px.w + a3);
        c = fg * c + ig * ftanh(px.z + a2);
        const float hn = og * ftanh(c);

        if (lane == 0) h8[w] = hn;
        __syncthreads();                      // h8 complete; hsm reusable

        if (tid < 2) {                        // publish FIRST via 2x STG.128
            const float4 v = ((const float4*)h8)[tid];
            float* dst = &g_hseq[t + 1][dir][sub * UPB + tid * 4];
            asm volatile("st.volatile.global.v4.f32 [%0], {%1,%2,%3,%4};"
                         :: "l"(dst), "f"(v.x), "f"(v.y), "f"(v.z), "f"(v.w)
                         : "memory");
        }
        if (lane == 0) {                      // archival store AFTER publish
            const int trow = dir ? (TT - 1 - t) : t;
            g_hs[trow][dir * HH + gu] = hn;
        }
        px = pn;
    }
}

// ---------------------------------------------------------------------------
// Kernel 3: feats = [hs_f | hs_b] @ W_out^T + b_out   (grid = T, 256 threads)
// ---------------------------------------------------------------------------
__global__ void feats_kernel(const float* __restrict__ Wout,
                             const float* __restrict__ bout) {
    __shared__ __align__(16) float hsm[2 * HH];
    const int t = blockIdx.x;
    const int tid = threadIdx.x, w = tid >> 5, lane = tid & 31;
    ((float4*)hsm)[tid] = ((const float4*)&g_hs[t][0])[tid];
    __syncthreads();
    if (w < KK) {
        float acc = 0.f;
        const float* wr = Wout + w * 2 * HH;
        for (int k = lane; k < 2 * HH; k += 32) acc += hsm[k] * __ldg(wr + k);
#pragma unroll
        for (int off = 16; off; off >>= 1) acc += __shfl_down_sync(0xffffffffu, acc, off);
        if (lane == 0) g_feats[t][w] = acc + bout[w];
    }
}

// ---------------------------------------------------------------------------
// Kernel 4: Viterbi forward + backtrace. 1 block, 128 threads; feats in SMEM.
// ---------------------------------------------------------------------------
__global__ void viterbi_kernel(const float* __restrict__ trans,
                               float* __restrict__ out) {
    extern __shared__ __align__(16) float fsm[];   // [TT][KK] = 57344 B
    __shared__ signed char bp[TT][8];
    __shared__ signed char path_s[TT];
    const int tid = threadIdx.x;
    const int lane = tid & 31;

    {
        const float4* src = (const float4*)&g_feats[0][0];
        float4* dst = (float4*)fsm;
        const int n4 = TT * KK / 4;   // 3584
        for (int i = tid; i < n4; i += blockDim.x) dst[i] = src[i];
    }
    __syncthreads();

    if (tid < 32) {
        float tr[KK];
        if (lane < KK) {
#pragma unroll
            for (int j = 0; j < KK; j++) tr[j] = trans[lane * KK + j];
        }
        float fv = (lane == START_TAG) ? 0.f : NEGV;
        float fvv[KK];
#pragma unroll
        for (int j = 0; j < KK; j++) fvv[j] = __shfl_sync(0xffffffffu, fv, j);

        for (int t = 0; t < TT; t++) {
            if (lane < KK) {
                float v[KK];
#pragma unroll
                for (int j = 0; j < KK; j++) v[j] = fvv[j] + tr[j];
                // left-biased tree argmax (== first-max over j)
                float m01 = v[0]; int i01 = 0;
                if (v[1] > m01) { m01 = v[1]; i01 = 1; }
                float m23 = v[2]; int i23 = 2;
                if (v[3] > m23) { m23 = v[3]; i23 = 3; }
                float m45 = v[4]; int i45 = 4;
                if (v[5] > m45) { m45 = v[5]; i45 = 5; }
                float mA = m01; int iA = i01;
                if (m23 > mA) { mA = m23; iA = i23; }
                float mB = m45; int iB = i45;
                if (v[6] > mB) { mB = v[6]; iB = 6; }
                float m = mA; int im = iA;
                if (mB > m) { m = mB; im = iB; }
                bp[t][lane] = (signed char)im;
                fv = m + fsm[t * KK + lane];
            }
#pragma unroll
            for (int j = 0; j < KK; j++) fvv[j] = __shfl_sync(0xffffffffu, fv, j);
        }

        if (lane == 0) {
            float best = -1e30f; int bi = 0;
#pragma unroll
            for (int i = 0; i < KK; i++) {
                float v = fvv[i] + trans[STOP_TAG * KK + i];
                if (v > best) { best = v; bi = i; }
            }
            out[0] = best;                         // path_score
            int tag = bi;
            for (int t = TT - 1; t >= 0; t--) {
                path_s[t] = (signed char)tag;
                tag = bp[t][tag];
            }
        }
    }
    __syncthreads();
    for (int t = tid; t < TT; t += blockDim.x) out[1 + t] = (float)path_s[t];
}

// ---------------------------------------------------------------------------
extern "C" void kernel_launch(void* const* d_in, const int* in_sizes, int n_in,
                              void* d_out, int out_size) {
    const float* embeds = (const float*)d_in[0];
    const float* h0     = (const float*)d_in[1];
    const float* c0     = (const float*)d_in[2];
    const float* Wihf   = (const float*)d_in[3];
    const float* Whhf   = (const float*)d_in[4];
    const float* bihf   = (const float*)d_in[5];
    const float* bhhf   = (const float*)d_in[6];
    const float* Wihb   = (const float*)d_in[7];
    const float* Whhb   = (const float*)d_in[8];
    const float* bihb   = (const float*)d_in[9];
    const float* bhhb   = (const float*)d_in[10];
    const float* Wout   = (const float*)d_in[11];
    const float* bout   = (const float*)d_in[12];
    const float* trans  = (const float*)d_in[13];
    float* out = (float*)d_out;

    const int vit_smem = TT * KK * (int)sizeof(float);   // 57344
    cudaFuncSetAttribute(viterbi_kernel,
                         cudaFuncAttributeMaxDynamicSharedMemorySize, vit_smem);

    prime_kernel<<<512, 256>>>();                        // index 0
    gemm_pre<<<dim3(GATES / GBN, TT / GBM, 2), 256>>>(   // index 1
        embeds, Wihf, Wihb, bihf, bhhf, bihb, bhhb);
    noop_kernel<<<1, 32>>>();                            // index 2 (spacer)
    lstm_rec<<<dim3(CPD, 2), 256>>>(h0, c0, Whhf, Whhb); // index 3 -> ncu
    feats_kernel<<<TT, 256>>>(Wout, bout);               // index 4
    viterbi_kernel<<<1, 128, vit_smem>>>(trans, out);    // index 5
}